// round 15
// baseline (speedup 1.0000x reference)
#include <cuda_runtime.h>
#include <cuda_fp16.h>
#include <cstdint>

#define NN 100000
#define NE 1600000
#define DD 128
#define NP 500000
#define NG4 (NN * 32)   // gather work items (float4 granularity)

// ---- scratch (device globals) ----
__device__ __align__(16) float g_x[NN * DD];        // final node features (linkpred input)
__device__ __align__(16) float g_xnorm[NN * DD];    // fp32 aggregate input
// fp16 hi/lo split planes (GEMM A operands)
__device__ __align__(16) __half g_xs_hi[NN * DD];
__device__ __align__(16) __half g_xs_lo[NN * DD];
__device__ __align__(16) __half g_as_hi[NN * DD];
__device__ __align__(16) __half g_as_lo[NN * DD];
__device__ __align__(16) __half g_hs_hi[NN * DD];
__device__ __align__(16) __half g_hs_lo[NN * DD];
// pair-product split planes (linkpred GEMM A)
__device__ __align__(16) __half g_zs_hi[NP * DD];
__device__ __align__(16) __half g_zs_lo[NP * DD];
__device__ int g_deg_s[NN];
__device__ int g_deg_r[NN];
__device__ int g_rowstart[NN + 1];
__device__ int g_cursor[NN];
__device__ int g_esrc[NE];
__device__ unsigned g_ticket;
// transposed fp16 weights: Wt[n][k] = W[k][n]
__device__ __align__(16) __half g_w1t[DD * 256];
__device__ __align__(16) __half g_w2t[DD * 256];
__device__ __align__(16) __half g_wat[DD * DD];

// ---- helpers ----
__device__ __forceinline__ uint32_t smem_u32(const void* p) {
    uint32_t a;
    asm("{.reg .u64 t; cvta.to.shared.u64 t, %1; cvt.u32.u64 %0, t;}" : "=r"(a) : "l"(p));
    return a;
}
#define LDSM_X4(r, a) \
    asm volatile("ldmatrix.sync.aligned.m8n8.x4.shared.b16 {%0,%1,%2,%3}, [%4];" \
        : "=r"((r)[0]), "=r"((r)[1]), "=r"((r)[2]), "=r"((r)[3]) : "r"(a))
__device__ __forceinline__ void hmma(float* d, const uint32_t* a, const uint32_t* b) {
    asm volatile(
        "mma.sync.aligned.m16n8k16.row.col.f32.f16.f16.f32 "
        "{%0,%1,%2,%3}, {%4,%5,%6,%7}, {%8,%9}, {%0,%1,%2,%3};"
        : "+f"(d[0]), "+f"(d[1]), "+f"(d[2]), "+f"(d[3])
        : "r"(a[0]), "r"(a[1]), "r"(a[2]), "r"(a[3]), "r"(b[0]), "r"(b[1]));
}
// fp16 hi/lo split via packed cvt.rn.f16x2.f32 — bit-identical to scalar __float2half_rn
__device__ __forceinline__ uint32_t pack_h2(float a, float b, uint32_t& lo_out) {
    __half2 h = __floats2half2_rn(a, b);
    float2 hf = __half22float2(h);
    __half2 l = __floats2half2_rn(a - hf.x, b - hf.y);
    lo_out = *reinterpret_cast<uint32_t*>(&l);
    return *reinterpret_cast<uint32_t*>(&h);
}
#define CP_ASYNC16(dst, src) \
    asm volatile("cp.async.cg.shared.global [%0], [%1], 16;" :: "r"(dst), "l"(src))
#define CP_COMMIT() asm volatile("cp.async.commit_group;" ::: "memory")
#define CP_WAIT_1() asm volatile("cp.async.wait_group 1;" ::: "memory")
#define CP_WAIT_0() asm volatile("cp.async.wait_group 0;" ::: "memory")

#define RS 80                 // smem row stride in bytes (conflict-free for ldmatrix)
#define BUF (128 * RS)        // 10240 B per matrix buffer
#define STG3 (3 * BUF)        // Ah+Al+B per stage
#define DSMEM_LG (3 * STG3)   // 3-stage ring = 90KB (layer gemm AND linkgemm)

// ---------------------------------------------------------------------------
// 1) prep: transpose+convert weights to fp16, init degree arrays, reset ticket
__global__ void k_prep_all(const float* __restrict__ W1, const float* __restrict__ W2,
                           const float* __restrict__ Wa) {
    int i = blockIdx.x * blockDim.x + threadIdx.x;
    if (i < DD * 256) {
        int n = i >> 8, k = i & 255;
        g_w1t[i] = __float2half_rn(W1[k * DD + n]);
        g_w2t[i] = __float2half_rn(W2[k * DD + n]);
    }
    if (i < DD * DD) {
        int n = i >> 7, k = i & 127;
        g_wat[i] = __float2half_rn(Wa[k * DD + n]);
    }
    if (i < NN) { g_deg_s[i] = 1; g_deg_r[i] = 1; }
    if (i == 0) g_ticket = 0;
}

// 2) count degrees; last block performs the exclusive scan (ticket pattern)
__global__ void k_count_scan(const int* __restrict__ senders, const int* __restrict__ receivers) {
    int stride = gridDim.x * blockDim.x;
    for (int e = blockIdx.x * blockDim.x + threadIdx.x; e < NE; e += stride) {
        atomicAdd(&g_deg_s[senders[e]], 1);
        atomicAdd(&g_deg_r[receivers[e]], 1);
    }
    __threadfence();
    __shared__ unsigned s_last;
    __syncthreads();
    if (threadIdx.x == 0) s_last = atomicAdd(&g_ticket, 1);
    __syncthreads();
    if (s_last != gridDim.x - 1) return;

    __shared__ int ss[256];
    int t = threadIdx.x;
    const int chunk = (NN + 255) / 256;
    int beg = t * chunk;
    int end = beg + chunk; if (end > NN) end = NN;
    int s = 0;
    for (int i = beg; i < end; i++) s += __ldcg(&g_deg_r[i]) - 1;
    ss[t] = s;
    __syncthreads();
    for (int off = 1; off < 256; off <<= 1) {
        int v = (t >= off) ? ss[t - off] : 0;
        __syncthreads();
        ss[t] += v;
        __syncthreads();
    }
    int run = (t == 0) ? 0 : ss[t - 1];
    for (int i = beg; i < end; i++) {
        g_rowstart[i] = run;
        g_cursor[i] = run;
        run += __ldcg(&g_deg_r[i]) - 1;
    }
    if (t == 255) g_rowstart[NN] = ss[255];
}

// 3) fused: CSR scatter + gather (emb -> x split planes + xnorm fp32)
__global__ void k_scatter_gather(const int* __restrict__ senders,
                                 const int* __restrict__ receivers,
                                 const int* __restrict__ node_ids,
                                 const float* __restrict__ emb) {
    int i = blockIdx.x * blockDim.x + threadIdx.x;
    if (i < NG4) {
        int node = i >> 5;
        int q = i & 31;
        int src = node_ids[node];
        float4 v = ((const float4*)emb)[src * 32 + q];
        uint32_t l0, l1;
        uint2 H;
        H.x = pack_h2(v.x, v.y, l0);
        H.y = pack_h2(v.z, v.w, l1);
        ((uint2*)g_xs_hi)[i] = H;
        ((uint2*)g_xs_lo)[i] = make_uint2(l0, l1);
        float sc = rsqrtf((float)g_deg_s[node]);
        v.x *= sc; v.y *= sc; v.z *= sc; v.w *= sc;
        ((float4*)g_xnorm)[i] = v;
    } else {
        int e = i - NG4;
        if (e < NE) {
            int r = receivers[e];
            int pos = atomicAdd(&g_cursor[r], 1);
            g_esrc[pos] = senders[e];
        }
    }
}

__device__ __forceinline__ float4 f4add(float4 a, float4 b) {
    return make_float4(a.x + b.x, a.y + b.y, a.z + b.z, a.w + b.w);
}

// 4) aggregate: warp per node; writes agg as fp16 hi/lo planes
__global__ void k_aggregate() {
    int gw = (blockIdx.x * blockDim.x + threadIdx.x) >> 5;
    if (gw >= NN) return;
    int lane = threadIdx.x & 31;
    const float4* __restrict__ xn = (const float4*)g_xnorm;
    float4 acc = xn[gw * 32 + lane];
    int s = g_rowstart[gw], e = g_rowstart[gw + 1];
    int j = s;
    for (; j + 8 <= e; j += 8) {
        int s0 = g_esrc[j], s1 = g_esrc[j + 1], s2 = g_esrc[j + 2], s3 = g_esrc[j + 3];
        int s4 = g_esrc[j + 4], s5 = g_esrc[j + 5], s6 = g_esrc[j + 6], s7 = g_esrc[j + 7];
        float4 a0 = xn[s0 * 32 + lane];
        float4 a1 = xn[s1 * 32 + lane];
        float4 a2 = xn[s2 * 32 + lane];
        float4 a3 = xn[s3 * 32 + lane];
        float4 a4 = xn[s4 * 32 + lane];
        float4 a5 = xn[s5 * 32 + lane];
        float4 a6 = xn[s6 * 32 + lane];
        float4 a7 = xn[s7 * 32 + lane];
        acc = f4add(acc, f4add(f4add(f4add(a0, a1), f4add(a2, a3)),
                               f4add(f4add(a4, a5), f4add(a6, a7))));
    }
    for (; j < e; j++) acc = f4add(acc, xn[g_esrc[j] * 32 + lane]);
    float cnt = (float)(e - s + 1);
    float sc = rsqrtf(cnt) / cnt;
    acc.x *= sc; acc.y *= sc; acc.z *= sc; acc.w *= sc;
    uint32_t l0, l1;
    uint2 H;
    H.x = pack_h2(acc.x, acc.y, l0);
    H.y = pack_h2(acc.z, acc.w, l1);
    ((uint2*)g_as_hi)[gw * 32 + lane] = H;
    ((uint2*)g_as_lo)[gw * 32 + lane] = make_uint2(l0, l1);
}

// 5) pair products: z = x[ia]*x[ib] -> fp16 hi/lo planes (barrier-free stream)
__global__ void k_pairprod(const float* __restrict__ H, const int* __restrict__ pairs) {
    int i = blockIdx.x * blockDim.x + threadIdx.x;
    if (i >= NP * 32) return;
    int p = i >> 5, q = i & 31;
    int ia = pairs[2 * p], ib = pairs[2 * p + 1];
    float4 x = ((const float4*)(H + ia * DD))[q];
    float4 y = ((const float4*)(H + ib * DD))[q];
    float4 v = make_float4(x.x * y.x, x.y * y.y, x.z * y.z, x.w * y.w);
    uint32_t l0, l1;
    uint2 Hh;
    Hh.x = pack_h2(v.x, v.y, l0);
    Hh.y = pack_h2(v.z, v.w, l1);
    ((uint2*)g_zs_hi)[i] = Hh;
    ((uint2*)g_zs_lo)[i] = make_uint2(l0, l1);
}

// MMA compute for one staged chunk (fp16, 2-term split on A)
__device__ __forceinline__ void chunk_compute(
    float (*acc)[8][4], uint32_t aHi, uint32_t aLo, uint32_t aB,
    int wm, int wn, int lane)
{
    int a_row = lane & 15, a_k = (lane >> 4) * 16;
    int b_addr_row = (lane & 7) + 8 * ((lane >> 4) & 1);
    int b_k = ((lane >> 3) & 1) * 16;
#pragma unroll
    for (int ks = 0; ks < 2; ks++) {
        uint32_t ah[2][4], al[2][4], b[8][2];
#pragma unroll
        for (int mt = 0; mt < 2; mt++) {
            uint32_t ao = (uint32_t)((wm * 32 + mt * 16 + a_row) * RS + ks * 32 + a_k);
            LDSM_X4(ah[mt], aHi + ao);
            LDSM_X4(al[mt], aLo + ao);
        }
#pragma unroll
        for (int np = 0; np < 4; np++) {
            uint32_t bo = (uint32_t)((wn * 64 + np * 16 + b_addr_row) * RS + ks * 32 + b_k);
            uint32_t r4[4];
            LDSM_X4(r4, aB + bo);
            b[2 * np][0] = r4[0]; b[2 * np][1] = r4[1];
            b[2 * np + 1][0] = r4[2]; b[2 * np + 1][1] = r4[3];
        }
#pragma unroll
        for (int mt = 0; mt < 2; mt++)
#pragma unroll
            for (int nt = 0; nt < 8; nt++) {
                hmma(acc[mt][nt], ah[mt], b[nt]);
                hmma(acc[mt][nt], al[mt], b[nt]);
            }
    }
}

// ---- HMMA layer GEMM: cp.async 3-stage ring, ONE barrier per chunk, K=256 ----
template <bool RELU, bool WRITE_XN, bool SPLIT_OUT>
__global__ void __launch_bounds__(256, 2) k_mgemm_layer(
    const __half* __restrict__ Xhi, const __half* __restrict__ Xlo,
    const __half* __restrict__ Ahi, const __half* __restrict__ Alo,
    const __half* __restrict__ Bw, const float* __restrict__ bias,
    __half* __restrict__ Chi, __half* __restrict__ Clo, float* __restrict__ Cf,
    float* __restrict__ XN, const int* __restrict__ deg, int M)
{
    extern __shared__ __align__(16) uint8_t dsm[];
    int tid = threadIdx.x;
    int lane = tid & 31, wid = tid >> 5;
    int wm = wid & 3, wn = wid >> 2;
    int blk = blockIdx.x * 128;

    float acc[2][8][4];
#pragma unroll
    for (int mt = 0; mt < 2; mt++)
#pragma unroll
        for (int nt = 0; nt < 8; nt++)
#pragma unroll
            for (int i = 0; i < 4; i++) acc[mt][nt][i] = 0.f;

    int srow = tid >> 1, half = tid & 1;
    int grow_s = blk + srow;
    int crow_s = grow_s < M ? grow_s : M - 1;
    int off = srow * RS + half * 32;

    uint32_t sbase = smem_u32(dsm);
    const char* xh = (const char*)(Xhi + crow_s * DD) + half * 32;
    const char* xl = (const char*)(Xlo + crow_s * DD) + half * 32;
    const char* gh = (const char*)(Ahi + crow_s * DD) + half * 32;
    const char* gl = (const char*)(Alo + crow_s * DD) + half * 32;
    const char* bw = (const char*)(Bw + srow * 256) + half * 32;

    auto issue = [&](int c) {
        uint32_t st = sbase + (c % 3) * STG3 + off;
        int kb2 = (c & 3) * 64;
        const char* sh = (c < 4) ? xh : gh;
        const char* sl = (c < 4) ? xl : gl;
        CP_ASYNC16(st, sh + kb2);
        CP_ASYNC16(st + 16, sh + kb2 + 16);
        CP_ASYNC16(st + BUF, sl + kb2);
        CP_ASYNC16(st + BUF + 16, sl + kb2 + 16);
        CP_ASYNC16(st + 2 * BUF, bw + c * 64);
        CP_ASYNC16(st + 2 * BUF + 16, bw + c * 64 + 16);
        CP_COMMIT();
    };

    issue(0);
    issue(1);
#pragma unroll
    for (int c = 0; c < 8; c++) {
        if (c < 7) CP_WAIT_1(); else CP_WAIT_0();
        __syncthreads();
        if (c + 2 <= 7) issue(c + 2);
        uint32_t st = sbase + (c % 3) * STG3;
        chunk_compute(acc, st, st + BUF, st + 2 * BUF, wm, wn, lane);
    }

    // epilogue
#pragma unroll
    for (int mt = 0; mt < 2; mt++) {
        int r0 = blk + wm * 32 + mt * 16 + (lane >> 2);
        int r1 = r0 + 8;
        float s0 = 1.f, s1 = 1.f;
        if (WRITE_XN) {
            s0 = rsqrtf((float)deg[r0 < M ? r0 : M - 1]);
            s1 = rsqrtf((float)deg[r1 < M ? r1 : M - 1]);
        }
#pragma unroll
        for (int nt = 0; nt < 8; nt++) {
            int cc = wn * 64 + nt * 8 + (lane & 3) * 2;
            float2 bv = *(const float2*)(bias + cc);
            float v0 = acc[mt][nt][0] + bv.x;
            float v1 = acc[mt][nt][1] + bv.y;
            float v2 = acc[mt][nt][2] + bv.x;
            float v3 = acc[mt][nt][3] + bv.y;
            if (RELU) {
                v0 = fmaxf(v0, 0.f); v1 = fmaxf(v1, 0.f);
                v2 = fmaxf(v2, 0.f); v3 = fmaxf(v3, 0.f);
            }
            if (r0 < M) {
                if (SPLIT_OUT) {
                    uint32_t lo;
                    uint32_t hi = pack_h2(v0, v1, lo);
                    *(uint32_t*)((char*)Chi + r0 * 256 + cc * 2) = hi;
                    *(uint32_t*)((char*)Clo + r0 * 256 + cc * 2) = lo;
                } else {
                    *(float2*)(Cf + r0 * DD + cc) = make_float2(v0, v1);
                }
                if (WRITE_XN) *(float2*)(XN + r0 * DD + cc) = make_float2(v0 * s0, v1 * s0);
            }
            if (r1 < M) {
                if (SPLIT_OUT) {
                    uint32_t lo;
                    uint32_t hi = pack_h2(v2, v3, lo);
                    *(uint32_t*)((char*)Chi + r1 * 256 + cc * 2) = hi;
                    *(uint32_t*)((char*)Clo + r1 * 256 + cc * 2) = lo;
                } else {
                    *(float2*)(Cf + r1 * DD + cc) = make_float2(v2, v3);
                }
                if (WRITE_XN) *(float2*)(XN + r1 * DD + cc) = make_float2(v2 * s1, v3 * s1);
            }
        }
    }
}

// ---- linkpred dense GEMM: A = pre-split z planes, K=128, reduce epilogue ----
__global__ void __launch_bounds__(256, 2) k_mlinkgemm(
    const __half* __restrict__ Zhi, const __half* __restrict__ Zlo,
    const __half* __restrict__ Bw,
    const float* __restrict__ ba, const float* __restrict__ Wb,
    const float* __restrict__ bb, float* __restrict__ out)
{
    extern __shared__ __align__(16) uint8_t dsm[];
    __shared__ float sacc[128];
    int tid = threadIdx.x;
    int lane = tid & 31, wid = tid >> 5;
    int wm = wid & 3, wn = wid >> 2;
    int blk = blockIdx.x * 128;

    if (tid < 128) sacc[tid] = 0.f;

    float acc[2][8][4];
#pragma unroll
    for (int mt = 0; mt < 2; mt++)
#pragma unroll
        for (int nt = 0; nt < 8; nt++)
#pragma unroll
            for (int i = 0; i < 4; i++) acc[mt][nt][i] = 0.f;

    int srow = tid >> 1, half = tid & 1;
    int grow_s = blk + srow;
    int crow_s = grow_s < NP ? grow_s : NP - 1;
    int off = srow * RS + half * 32;

    uint32_t sbase = smem_u32(dsm);
    const char* zh = (const char*)(Zhi + crow_s * DD) + half * 32;
    const char* zl = (const char*)(Zlo + crow_s * DD) + half * 32;
    const char* bw = (const char*)(Bw + srow * DD) + half * 32;

    auto issue = [&](int c) {
        uint32_t st = sbase + (c % 3) * STG3 + off;
        CP_ASYNC16(st, zh + c * 64);
        CP_ASYNC16(st + 16, zh + c * 64 + 16);
        CP_ASYNC16(st + BUF, zl + c * 64);
        CP_ASYNC16(st + BUF + 16, zl + c * 64 + 16);
        CP_ASYNC16(st + 2 * BUF, bw + c * 64);
        CP_ASYNC16(st + 2 * BUF + 16, bw + c * 64 + 16);
        CP_COMMIT();
    };

    issue(0);
    issue(1);
#pragma unroll
    for (int c = 0; c < 4; c++) {
        if (c < 3) CP_WAIT_1(); else CP_WAIT_0();
        __syncthreads();
        if (c + 2 <= 3) issue(c + 2);
        uint32_t st = sbase + (c % 3) * STG3;
        chunk_compute(acc, st, st + BUF, st + 2 * BUF, wm, wn, lane);
    }

    // epilogue: per-row sum of relu(acc + ba[c]) * Wb[c]
#pragma unroll
    for (int mt = 0; mt < 2; mt++) {
        int lr0 = wm * 32 + mt * 16 + (lane >> 2);
        float p0 = 0.f, p1 = 0.f;
#pragma unroll
        for (int nt = 0; nt < 8; nt++) {
            int cc = wn * 64 + nt * 8 + (lane & 3) * 2;
            float2 bav = *(const float2*)(ba + cc);
            float2 wbv = *(const float2*)(Wb + cc);
            p0 += fmaxf(acc[mt][nt][0] + bav.x, 0.f) * wbv.x
                + fmaxf(acc[mt][nt][1] + bav.y, 0.f) * wbv.y;
            p1 += fmaxf(acc[mt][nt][2] + bav.x, 0.f) * wbv.x
                + fmaxf(acc[mt][nt][3] + bav.y, 0.f) * wbv.y;
        }
        p0 += __shfl_xor_sync(0xffffffffu, p0, 1);
        p0 += __shfl_xor_sync(0xffffffffu, p0, 2);
        p1 += __shfl_xor_sync(0xffffffffu, p1, 1);
        p1 += __shfl_xor_sync(0xffffffffu, p1, 2);
        if ((lane & 3) == 0) {
            atomicAdd(&sacc[lr0], p0);
            atomicAdd(&sacc[lr0 + 8], p1);
        }
    }
    __syncthreads();
    if (tid < 128) {
        int row = blk + tid;
        if (row < NP) out[row] = sacc[tid] + bb[0];
    }
}

// ---------------------------------------------------------------------------
extern "C" void kernel_launch(void* const* d_in, const int* in_sizes, int n_in,
                              void* d_out, int out_size) {
    const int*   node_ids  = (const int*)d_in[0];
    const int*   senders   = (const int*)d_in[1];
    const int*   receivers = (const int*)d_in[2];
    const int*   pairs     = (const int*)d_in[3];
    const float* emb       = (const float*)d_in[4];
    const float* W1        = (const float*)d_in[5];
    const float* b1        = (const float*)d_in[6];
    const float* W2        = (const float*)d_in[7];
    const float* b2        = (const float*)d_in[8];
    const float* Wa        = (const float*)d_in[9];
    const float* ba        = (const float*)d_in[10];
    const float* Wb        = (const float*)d_in[11];
    const float* bb        = (const float*)d_in[12];
    float* out = (float*)d_out;

    float *x, *xn;
    int* degs;
    __half *w1t, *w2t, *wat, *xsh, *xsl, *ash, *asl, *hsh, *hsl, *zsh, *zsl;
    cudaGetSymbolAddress((void**)&x,  g_x);
    cudaGetSymbolAddress((void**)&xn, g_xnorm);
    cudaGetSymbolAddress((void**)&degs, g_deg_s);
    cudaGetSymbolAddress((void**)&w1t, g_w1t);
    cudaGetSymbolAddress((void**)&w2t, g_w2t);
    cudaGetSymbolAddress((void**)&wat, g_wat);
    cudaGetSymbolAddress((void**)&xsh, g_xs_hi);
    cudaGetSymbolAddress((void**)&xsl, g_xs_lo);
    cudaGetSymbolAddress((void**)&ash, g_as_hi);
    cudaGetSymbolAddress((void**)&asl, g_as_lo);
    cudaGetSymbolAddress((void**)&hsh, g_hs_hi);
    cudaGetSymbolAddress((void**)&hsl, g_hs_lo);
    cudaGetSymbolAddress((void**)&zsh, g_zs_hi);
    cudaGetSymbolAddress((void**)&zsl, g_zs_lo);

    cudaFuncSetAttribute(k_mgemm_layer<true, true, true>,
                         cudaFuncAttributeMaxDynamicSharedMemorySize, DSMEM_LG);
    cudaFuncSetAttribute(k_mgemm_layer<false, false, false>,
                         cudaFuncAttributeMaxDynamicSharedMemorySize, DSMEM_LG);
    cudaFuncSetAttribute(k_mlinkgemm,
                         cudaFuncAttributeMaxDynamicSharedMemorySize, DSMEM_LG);

    const int vb = (NG4 + 255) / 256;   // 12500

    k_prep_all<<<(NN + 255) / 256, 256>>>(W1, W2, Wa);
    k_count_scan<<<2048, 256>>>(senders, receivers);
    k_scatter_gather<<<(NG4 + NE + 255) / 256, 256>>>(senders, receivers, node_ids, emb);
    k_aggregate<<<vb, 256>>>();

    // layer 1: [x|agg] -> h split planes (relu) + xnorm fp32 for layer-2 aggregate
    k_mgemm_layer<true, true, true><<<(NN + 127) / 128, 256, DSMEM_LG>>>(
        xsh, xsl, ash, asl, w1t, b1, hsh, hsl, nullptr, xn, degs, NN);

    // layer 2: [h|agg] -> x fp32 (no relu)
    k_aggregate<<<vb, 256>>>();
    k_mgemm_layer<false, false, false><<<(NN + 127) / 128, 256, DSMEM_LG>>>(
        hsh, hsl, ash, asl, w2t, b2, nullptr, nullptr, x, nullptr, degs, NN);

    // link predictor: product stream + dense pipelined GEMM
    k_pairprod<<<(NP * 32 + 255) / 256, 256>>>(x, pairs);
    k_mlinkgemm<<<(NP + 127) / 128, 256, DSMEM_LG>>>(
        zsh, zsl, wat, ba, Wb, bb, out);
}

// round 16
// speedup vs baseline: 1.0478x; 1.0478x over previous
#include <cuda_runtime.h>
#include <cuda_fp16.h>
#include <cstdint>

#define NN 100000
#define NE 1600000
#define DD 128
#define NP 500000
#define NG4 (NN * 32)   // gather work items (float4 granularity)

// ---- scratch (device globals) ----
__device__ __align__(16) float g_x[NN * DD];        // final node features (linkpred input)
__device__ __align__(16) float g_xnorm[NN * DD];    // fp32 aggregate input
// fp16 hi/lo split planes (GEMM A operands)
__device__ __align__(16) __half g_xs_hi[NN * DD];
__device__ __align__(16) __half g_xs_lo[NN * DD];
__device__ __align__(16) __half g_as_hi[NN * DD];
__device__ __align__(16) __half g_as_lo[NN * DD];
__device__ __align__(16) __half g_hs_hi[NN * DD];
__device__ __align__(16) __half g_hs_lo[NN * DD];
__device__ int g_deg_s[NN];
__device__ int g_deg_r[NN];
__device__ int g_rowstart[NN + 1];
__device__ int g_cursor[NN];
__device__ int g_esrc[NE];
__device__ unsigned g_ticket;
// transposed fp16 weights: Wt[n][k] = W[k][n]
__device__ __align__(16) __half g_w1t[DD * 256];
__device__ __align__(16) __half g_w2t[DD * 256];
__device__ __align__(16) __half g_wat[DD * DD];

// ---- helpers ----
__device__ __forceinline__ uint32_t smem_u32(const void* p) {
    uint32_t a;
    asm("{.reg .u64 t; cvta.to.shared.u64 t, %1; cvt.u32.u64 %0, t;}" : "=r"(a) : "l"(p));
    return a;
}
#define LDSM_X4(r, a) \
    asm volatile("ldmatrix.sync.aligned.m8n8.x4.shared.b16 {%0,%1,%2,%3}, [%4];" \
        : "=r"((r)[0]), "=r"((r)[1]), "=r"((r)[2]), "=r"((r)[3]) : "r"(a))
__device__ __forceinline__ void hmma(float* d, const uint32_t* a, const uint32_t* b) {
    asm volatile(
        "mma.sync.aligned.m16n8k16.row.col.f32.f16.f16.f32 "
        "{%0,%1,%2,%3}, {%4,%5,%6,%7}, {%8,%9}, {%0,%1,%2,%3};"
        : "+f"(d[0]), "+f"(d[1]), "+f"(d[2]), "+f"(d[3])
        : "r"(a[0]), "r"(a[1]), "r"(a[2]), "r"(a[3]), "r"(b[0]), "r"(b[1]));
}
// fp16 hi/lo split via packed cvt.rn.f16x2.f32 — bit-identical to scalar __float2half_rn
__device__ __forceinline__ uint32_t pack_h2(float a, float b, uint32_t& lo_out) {
    __half2 h = __floats2half2_rn(a, b);
    float2 hf = __half22float2(h);
    __half2 l = __floats2half2_rn(a - hf.x, b - hf.y);
    lo_out = *reinterpret_cast<uint32_t*>(&l);
    return *reinterpret_cast<uint32_t*>(&h);
}
#define CP_ASYNC16(dst, src) \
    asm volatile("cp.async.cg.shared.global [%0], [%1], 16;" :: "r"(dst), "l"(src))
#define CP_COMMIT() asm volatile("cp.async.commit_group;" ::: "memory")
#define CP_WAIT_1() asm volatile("cp.async.wait_group 1;" ::: "memory")
#define CP_WAIT_0() asm volatile("cp.async.wait_group 0;" ::: "memory")
#define CP_WAIT_ALL() asm volatile("cp.async.wait_all;" ::: "memory")

#define RS 80                 // smem row stride in bytes (conflict-free for ldmatrix)
#define BUF (128 * RS)        // 10240 B per matrix buffer
#define STG3 (3 * BUF)        // Ah+Al+B per stage
#define DSMEM_LG (3 * STG3)   // layer gemm: 3-stage ring = 90KB
#define DSMEM_LP (8 * BUF)    // linkpred: 4x B-chunks + 2x (Ah,Al) stages = 80KB

// ---------------------------------------------------------------------------
// 1) prep: transpose+convert weights to fp16, init degree arrays, reset ticket
__global__ void k_prep_all(const float* __restrict__ W1, const float* __restrict__ W2,
                           const float* __restrict__ Wa) {
    int i = blockIdx.x * blockDim.x + threadIdx.x;
    if (i < DD * 256) {
        int n = i >> 8, k = i & 255;
        g_w1t[i] = __float2half_rn(W1[k * DD + n]);
        g_w2t[i] = __float2half_rn(W2[k * DD + n]);
    }
    if (i < DD * DD) {
        int n = i >> 7, k = i & 127;
        g_wat[i] = __float2half_rn(Wa[k * DD + n]);
    }
    if (i < NN) { g_deg_s[i] = 1; g_deg_r[i] = 1; }
    if (i == 0) g_ticket = 0;
}

// 2) count degrees; last block performs the exclusive scan (ticket pattern)
__global__ void k_count_scan(const int* __restrict__ senders, const int* __restrict__ receivers) {
    int stride = gridDim.x * blockDim.x;
    for (int e = blockIdx.x * blockDim.x + threadIdx.x; e < NE; e += stride) {
        atomicAdd(&g_deg_s[senders[e]], 1);
        atomicAdd(&g_deg_r[receivers[e]], 1);
    }
    __threadfence();
    __shared__ unsigned s_last;
    __syncthreads();
    if (threadIdx.x == 0) s_last = atomicAdd(&g_ticket, 1);
    __syncthreads();
    if (s_last != gridDim.x - 1) return;

    __shared__ int ss[256];
    int t = threadIdx.x;
    const int chunk = (NN + 255) / 256;
    int beg = t * chunk;
    int end = beg + chunk; if (end > NN) end = NN;
    int s = 0;
    for (int i = beg; i < end; i++) s += __ldcg(&g_deg_r[i]) - 1;
    ss[t] = s;
    __syncthreads();
    for (int off = 1; off < 256; off <<= 1) {
        int v = (t >= off) ? ss[t - off] : 0;
        __syncthreads();
        ss[t] += v;
        __syncthreads();
    }
    int run = (t == 0) ? 0 : ss[t - 1];
    for (int i = beg; i < end; i++) {
        g_rowstart[i] = run;
        g_cursor[i] = run;
        run += __ldcg(&g_deg_r[i]) - 1;
    }
    if (t == 255) g_rowstart[NN] = ss[255];
}

// 3) fused: CSR scatter + gather (emb -> x split planes + xnorm fp32)
//    NOTE: g_x is NOT written here — layer-1 consumes the split planes and
//    gemm2 fully overwrites g_x before linkpred reads it (dead-store removed).
__global__ void k_scatter_gather(const int* __restrict__ senders,
                                 const int* __restrict__ receivers,
                                 const int* __restrict__ node_ids,
                                 const float* __restrict__ emb) {
    int i = blockIdx.x * blockDim.x + threadIdx.x;
    if (i < NG4) {
        int node = i >> 5;
        int q = i & 31;
        int src = node_ids[node];
        float4 v = ((const float4*)emb)[src * 32 + q];
        uint32_t l0, l1;
        uint2 H;
        H.x = pack_h2(v.x, v.y, l0);
        H.y = pack_h2(v.z, v.w, l1);
        ((uint2*)g_xs_hi)[i] = H;
        ((uint2*)g_xs_lo)[i] = make_uint2(l0, l1);
        float sc = rsqrtf((float)g_deg_s[node]);
        v.x *= sc; v.y *= sc; v.z *= sc; v.w *= sc;
        ((float4*)g_xnorm)[i] = v;
    } else {
        int e = i - NG4;
        if (e < NE) {
            int r = receivers[e];
            int pos = atomicAdd(&g_cursor[r], 1);
            g_esrc[pos] = senders[e];
        }
    }
}

__device__ __forceinline__ float4 f4add(float4 a, float4 b) {
    return make_float4(a.x + b.x, a.y + b.y, a.z + b.z, a.w + b.w);
}

// 4) aggregate: warp per node; writes agg as fp16 hi/lo planes
__global__ void k_aggregate() {
    int gw = (blockIdx.x * blockDim.x + threadIdx.x) >> 5;
    if (gw >= NN) return;
    int lane = threadIdx.x & 31;
    const float4* __restrict__ xn = (const float4*)g_xnorm;
    float4 acc = xn[gw * 32 + lane];
    int s = g_rowstart[gw], e = g_rowstart[gw + 1];
    int j = s;
    for (; j + 8 <= e; j += 8) {
        int s0 = g_esrc[j], s1 = g_esrc[j + 1], s2 = g_esrc[j + 2], s3 = g_esrc[j + 3];
        int s4 = g_esrc[j + 4], s5 = g_esrc[j + 5], s6 = g_esrc[j + 6], s7 = g_esrc[j + 7];
        float4 a0 = xn[s0 * 32 + lane];
        float4 a1 = xn[s1 * 32 + lane];
        float4 a2 = xn[s2 * 32 + lane];
        float4 a3 = xn[s3 * 32 + lane];
        float4 a4 = xn[s4 * 32 + lane];
        float4 a5 = xn[s5 * 32 + lane];
        float4 a6 = xn[s6 * 32 + lane];
        float4 a7 = xn[s7 * 32 + lane];
        acc = f4add(acc, f4add(f4add(f4add(a0, a1), f4add(a2, a3)),
                               f4add(f4add(a4, a5), f4add(a6, a7))));
    }
    for (; j < e; j++) acc = f4add(acc, xn[g_esrc[j] * 32 + lane]);
    float cnt = (float)(e - s + 1);
    float sc = rsqrtf(cnt) / cnt;
    acc.x *= sc; acc.y *= sc; acc.z *= sc; acc.w *= sc;
    uint32_t l0, l1;
    uint2 H;
    H.x = pack_h2(acc.x, acc.y, l0);
    H.y = pack_h2(acc.z, acc.w, l1);
    ((uint2*)g_as_hi)[gw * 32 + lane] = H;
    ((uint2*)g_as_lo)[gw * 32 + lane] = make_uint2(l0, l1);
}

// MMA compute for one staged chunk (fp16, 2-term split on A)
__device__ __forceinline__ void chunk_compute(
    float (*acc)[8][4], uint32_t aHi, uint32_t aLo, uint32_t aB,
    int wm, int wn, int lane)
{
    int a_row = lane & 15, a_k = (lane >> 4) * 16;
    int b_addr_row = (lane & 7) + 8 * ((lane >> 4) & 1);
    int b_k = ((lane >> 3) & 1) * 16;
#pragma unroll
    for (int ks = 0; ks < 2; ks++) {
        uint32_t ah[2][4], al[2][4], b[8][2];
#pragma unroll
        for (int mt = 0; mt < 2; mt++) {
            uint32_t ao = (uint32_t)((wm * 32 + mt * 16 + a_row) * RS + ks * 32 + a_k);
            LDSM_X4(ah[mt], aHi + ao);
            LDSM_X4(al[mt], aLo + ao);
        }
#pragma unroll
        for (int np = 0; np < 4; np++) {
            uint32_t bo = (uint32_t)((wn * 64 + np * 16 + b_addr_row) * RS + ks * 32 + b_k);
            uint32_t r4[4];
            LDSM_X4(r4, aB + bo);
            b[2 * np][0] = r4[0]; b[2 * np][1] = r4[1];
            b[2 * np + 1][0] = r4[2]; b[2 * np + 1][1] = r4[3];
        }
#pragma unroll
        for (int mt = 0; mt < 2; mt++)
#pragma unroll
            for (int nt = 0; nt < 8; nt++) {
                hmma(acc[mt][nt], ah[mt], b[nt]);
                hmma(acc[mt][nt], al[mt], b[nt]);
            }
    }
}

// ---- HMMA layer GEMM: cp.async 3-stage ring, ONE barrier per chunk, K=256 ----
template <bool RELU, bool WRITE_XN, bool SPLIT_OUT>
__global__ void __launch_bounds__(256, 2) k_mgemm_layer(
    const __half* __restrict__ Xhi, const __half* __restrict__ Xlo,
    const __half* __restrict__ Ahi, const __half* __restrict__ Alo,
    const __half* __restrict__ Bw, const float* __restrict__ bias,
    __half* __restrict__ Chi, __half* __restrict__ Clo, float* __restrict__ Cf,
    float* __restrict__ XN, const int* __restrict__ deg, int M)
{
    extern __shared__ __align__(16) uint8_t dsm[];
    int tid = threadIdx.x;
    int lane = tid & 31, wid = tid >> 5;
    int wm = wid & 3, wn = wid >> 2;
    int blk = blockIdx.x * 128;

    float acc[2][8][4];
#pragma unroll
    for (int mt = 0; mt < 2; mt++)
#pragma unroll
        for (int nt = 0; nt < 8; nt++)
#pragma unroll
            for (int i = 0; i < 4; i++) acc[mt][nt][i] = 0.f;

    int srow = tid >> 1, half = tid & 1;
    int grow_s = blk + srow;
    int crow_s = grow_s < M ? grow_s : M - 1;
    int off = srow * RS + half * 32;

    uint32_t sbase = smem_u32(dsm);
    const char* xh = (const char*)(Xhi + crow_s * DD) + half * 32;
    const char* xl = (const char*)(Xlo + crow_s * DD) + half * 32;
    const char* gh = (const char*)(Ahi + crow_s * DD) + half * 32;
    const char* gl = (const char*)(Alo + crow_s * DD) + half * 32;
    const char* bw = (const char*)(Bw + srow * 256) + half * 32;

    auto issue = [&](int c) {
        uint32_t st = sbase + (c % 3) * STG3 + off;
        int kb2 = (c & 3) * 64;
        const char* sh = (c < 4) ? xh : gh;
        const char* sl = (c < 4) ? xl : gl;
        CP_ASYNC16(st, sh + kb2);
        CP_ASYNC16(st + 16, sh + kb2 + 16);
        CP_ASYNC16(st + BUF, sl + kb2);
        CP_ASYNC16(st + BUF + 16, sl + kb2 + 16);
        CP_ASYNC16(st + 2 * BUF, bw + c * 64);
        CP_ASYNC16(st + 2 * BUF + 16, bw + c * 64 + 16);
        CP_COMMIT();
    };

    issue(0);
    issue(1);
#pragma unroll
    for (int c = 0; c < 8; c++) {
        if (c < 7) CP_WAIT_1(); else CP_WAIT_0();
        __syncthreads();
        if (c + 2 <= 7) issue(c + 2);
        uint32_t st = sbase + (c % 3) * STG3;
        chunk_compute(acc, st, st + BUF, st + 2 * BUF, wm, wn, lane);
    }

    // epilogue
#pragma unroll
    for (int mt = 0; mt < 2; mt++) {
        int r0 = blk + wm * 32 + mt * 16 + (lane >> 2);
        int r1 = r0 + 8;
        float s0 = 1.f, s1 = 1.f;
        if (WRITE_XN) {
            s0 = rsqrtf((float)deg[r0 < M ? r0 : M - 1]);
            s1 = rsqrtf((float)deg[r1 < M ? r1 : M - 1]);
        }
#pragma unroll
        for (int nt = 0; nt < 8; nt++) {
            int cc = wn * 64 + nt * 8 + (lane & 3) * 2;
            float2 bv = *(const float2*)(bias + cc);
            float v0 = acc[mt][nt][0] + bv.x;
            float v1 = acc[mt][nt][1] + bv.y;
            float v2 = acc[mt][nt][2] + bv.x;
            float v3 = acc[mt][nt][3] + bv.y;
            if (RELU) {
                v0 = fmaxf(v0, 0.f); v1 = fmaxf(v1, 0.f);
                v2 = fmaxf(v2, 0.f); v3 = fmaxf(v3, 0.f);
            }
            if (r0 < M) {
                if (SPLIT_OUT) {
                    uint32_t lo;
                    uint32_t hi = pack_h2(v0, v1, lo);
                    *(uint32_t*)((char*)Chi + r0 * 256 + cc * 2) = hi;
                    *(uint32_t*)((char*)Clo + r0 * 256 + cc * 2) = lo;
                } else {
                    *(float2*)(Cf + r0 * DD + cc) = make_float2(v0, v1);
                }
                if (WRITE_XN) *(float2*)(XN + r0 * DD + cc) = make_float2(v0 * s0, v1 * s0);
            }
            if (r1 < M) {
                if (SPLIT_OUT) {
                    uint32_t lo;
                    uint32_t hi = pack_h2(v2, v3, lo);
                    *(uint32_t*)((char*)Chi + r1 * 256 + cc * 2) = hi;
                    *(uint32_t*)((char*)Clo + r1 * 256 + cc * 2) = lo;
                } else {
                    *(float2*)(Cf + r1 * DD + cc) = make_float2(v2, v3);
                }
                if (WRITE_XN) *(float2*)(XN + r1 * DD + cc) = make_float2(v2 * s1, v3 * s1);
            }
        }
    }
}

// ---- HMMA link predictor, K=128: PERSISTENT 2 tiles per CTA, B prefetched once ----
__global__ void __launch_bounds__(256, 2) k_mlinkpred(
    const float* __restrict__ H, const int* __restrict__ pairs,
    const __half* __restrict__ Bw,
    const float* __restrict__ ba, const float* __restrict__ Wb,
    const float* __restrict__ bb, float* __restrict__ out)
{
    extern __shared__ __align__(16) uint8_t dsm[];
    __shared__ float sacc[128];
    int tid = threadIdx.x;
    int lane = tid & 31, wid = tid >> 5;
    int wm = wid & 3, wn = wid >> 2;
    int blk0 = blockIdx.x * 256;

    int srow = tid >> 1, half = tid & 1;
    int off = srow * RS + half * 32;

    // smem map: B chunks 0-3 at c*BUF; A stages at 4*BUF.. (Ah0,Al0,Ah1,Al1)
    uint32_t aB0 = smem_u32(dsm);
    uint32_t aAh0 = aB0 + 4 * BUF, aAl0 = aB0 + 5 * BUF;
    uint32_t aAh1 = aB0 + 6 * BUF, aAl1 = aB0 + 7 * BUF;

    // prefetch ALL of Wa ONCE (shared by both tiles)
    {
        const char* bw = (const char*)Bw + srow * 256 + half * 32;
#pragma unroll
        for (int c = 0; c < 4; c++) {
            CP_ASYNC16(aB0 + c * BUF + off, bw + c * 64);
            CP_ASYNC16(aB0 + c * BUF + off + 16, bw + c * 64 + 16);
        }
    }

    bool bwaited = false;
#pragma unroll
    for (int t = 0; t < 2; t++) {
        if (tid < 128) sacc[tid] = 0.f;

        int grow_s = blk0 + t * 128 + srow;
        int crow_s = grow_s < NP ? grow_s : NP - 1;
        int ia = pairs[2 * crow_s];
        int ib = pairs[2 * crow_s + 1];

        float acc[2][8][4];
#pragma unroll
        for (int mt = 0; mt < 2; mt++)
#pragma unroll
            for (int nt = 0; nt < 8; nt++)
#pragma unroll
                for (int i = 0; i < 4; i++) acc[mt][nt][i] = 0.f;

        // stage A (products -> fp16 hi/lo) for one chunk
        auto stageA = [&](int c, uint8_t* sAh, uint8_t* sAl) {
            int kb = c * 32;
            const float4* pa = (const float4*)(H + ia * DD + kb) + half * 4;
            const float4* pb = (const float4*)(H + ib * DD + kb) + half * 4;
            float4 pv[4];
#pragma unroll
            for (int i = 0; i < 4; i++) {
                float4 x = pa[i], y = pb[i];
                pv[i] = make_float4(x.x * y.x, x.y * y.y, x.z * y.z, x.w * y.w);
            }
            uint4 H0, L0, H1, L1;
            H0.x = pack_h2(pv[0].x, pv[0].y, L0.x);
            H0.y = pack_h2(pv[0].z, pv[0].w, L0.y);
            H0.z = pack_h2(pv[1].x, pv[1].y, L0.z);
            H0.w = pack_h2(pv[1].z, pv[1].w, L0.w);
            H1.x = pack_h2(pv[2].x, pv[2].y, L1.x);
            H1.y = pack_h2(pv[2].z, pv[2].w, L1.y);
            H1.z = pack_h2(pv[3].x, pv[3].y, L1.z);
            H1.w = pack_h2(pv[3].z, pv[3].w, L1.w);
            *(uint4*)(sAh + off) = H0;
            *(uint4*)(sAh + off + 16) = H1;
            *(uint4*)(sAl + off) = L0;
            *(uint4*)(sAl + off + 16) = L1;
        };

#pragma unroll
        for (int i = 0; i < 2; i++) {
            stageA(2 * i, dsm + 4 * BUF, dsm + 5 * BUF);
            stageA(2 * i + 1, dsm + 6 * BUF, dsm + 7 * BUF);
            if (!bwaited) { CP_WAIT_ALL(); bwaited = true; }   // B resident
            __syncthreads();
            chunk_compute(acc, aAh0, aAl0, aB0 + (2 * i) * BUF, wm, wn, lane);
            chunk_compute(acc, aAh1, aAl1, aB0 + (2 * i + 1) * BUF, wm, wn, lane);
            __syncthreads();
        }

        // epilogue: per-row sum of relu(acc + ba[c]) * Wb[c]
#pragma unroll
        for (int mt = 0; mt < 2; mt++) {
            int lr0 = wm * 32 + mt * 16 + (lane >> 2);
            float p0 = 0.f, p1 = 0.f;
#pragma unroll
            for (int nt = 0; nt < 8; nt++) {
                int cc = wn * 64 + nt * 8 + (lane & 3) * 2;
                float2 bav = *(const float2*)(ba + cc);
                float2 wbv = *(const float2*)(Wb + cc);
                p0 += fmaxf(acc[mt][nt][0] + bav.x, 0.f) * wbv.x
                    + fmaxf(acc[mt][nt][1] + bav.y, 0.f) * wbv.y;
                p1 += fmaxf(acc[mt][nt][2] + bav.x, 0.f) * wbv.x
                    + fmaxf(acc[mt][nt][3] + bav.y, 0.f) * wbv.y;
            }
            p0 += __shfl_xor_sync(0xffffffffu, p0, 1);
            p0 += __shfl_xor_sync(0xffffffffu, p0, 2);
            p1 += __shfl_xor_sync(0xffffffffu, p1, 1);
            p1 += __shfl_xor_sync(0xffffffffu, p1, 2);
            if ((lane & 3) == 0) {
                atomicAdd(&sacc[lr0], p0);
                atomicAdd(&sacc[lr0 + 8], p1);
            }
        }
        __syncthreads();
        if (tid < 128) {
            int row = blk0 + t * 128 + tid;
            if (row < NP) out[row] = sacc[tid] + bb[0];
        }
        __syncthreads();   // sacc reads complete before next tile resets it
    }
}

// ---------------------------------------------------------------------------
extern "C" void kernel_launch(void* const* d_in, const int* in_sizes, int n_in,
                              void* d_out, int out_size) {
    const int*   node_ids  = (const int*)d_in[0];
    const int*   senders   = (const int*)d_in[1];
    const int*   receivers = (const int*)d_in[2];
    const int*   pairs     = (const int*)d_in[3];
    const float* emb       = (const float*)d_in[4];
    const float* W1        = (const float*)d_in[5];
    const float* b1        = (const float*)d_in[6];
    const float* W2        = (const float*)d_in[7];
    const float* b2        = (const float*)d_in[8];
    const float* Wa        = (const float*)d_in[9];
    const float* ba        = (const float*)d_in[10];
    const float* Wb        = (const float*)d_in[11];
    const float* bb        = (const float*)d_in[12];
    float* out = (float*)d_out;

    float *x, *xn;
    int* degs;
    __half *w1t, *w2t, *wat, *xsh, *xsl, *ash, *asl, *hsh, *hsl;
    cudaGetSymbolAddress((void**)&x,  g_x);
    cudaGetSymbolAddress((void**)&xn, g_xnorm);
    cudaGetSymbolAddress((void**)&degs, g_deg_s);
    cudaGetSymbolAddress((void**)&w1t, g_w1t);
    cudaGetSymbolAddress((void**)&w2t, g_w2t);
    cudaGetSymbolAddress((void**)&wat, g_wat);
    cudaGetSymbolAddress((void**)&xsh, g_xs_hi);
    cudaGetSymbolAddress((void**)&xsl, g_xs_lo);
    cudaGetSymbolAddress((void**)&ash, g_as_hi);
    cudaGetSymbolAddress((void**)&asl, g_as_lo);
    cudaGetSymbolAddress((void**)&hsh, g_hs_hi);
    cudaGetSymbolAddress((void**)&hsl, g_hs_lo);

    cudaFuncSetAttribute(k_mgemm_layer<true, true, true>,
                         cudaFuncAttributeMaxDynamicSharedMemorySize, DSMEM_LG);
    cudaFuncSetAttribute(k_mgemm_layer<false, false, false>,
                         cudaFuncAttributeMaxDynamicSharedMemorySize, DSMEM_LG);
    cudaFuncSetAttribute(k_mlinkpred,
                         cudaFuncAttributeMaxDynamicSharedMemorySize, DSMEM_LP);

    const int vb = (NG4 + 255) / 256;   // 12500

    k_prep_all<<<(NN + 255) / 256, 256>>>(W1, W2, Wa);
    k_count_scan<<<2048, 256>>>(senders, receivers);
    k_scatter_gather<<<(NG4 + NE + 255) / 256, 256>>>(senders, receivers, node_ids, emb);
    k_aggregate<<<vb, 256>>>();

    // layer 1: [x|agg] -> h split planes (relu) + xnorm fp32 for layer-2 aggregate
    k_mgemm_layer<true, true, true><<<(NN + 127) / 128, 256, DSMEM_LG>>>(
        xsh, xsl, ash, asl, w1t, b1, hsh, hsl, nullptr, xn, degs, NN);

    // layer 2: [h|agg] -> x fp32 (no relu)
    k_aggregate<<<vb, 256>>>();
    k_mgemm_layer<false, false, false><<<(NN + 127) / 128, 256, DSMEM_LG>>>(
        hsh, hsl, ash, asl, w2t, b2, nullptr, nullptr, x, nullptr, degs, NN);

    // link predictor: persistent 2-tile CTAs
    k_mlinkpred<<<(NP + 255) / 256, 256, DSMEM_LP>>>(
        x, pairs, wat, ba, Wb, bb, out);
}

// round 17
// speedup vs baseline: 1.0669x; 1.0183x over previous
#include <cuda_runtime.h>
#include <cuda_fp16.h>
#include <cstdint>

#define NN 100000
#define NE 1600000
#define DD 128
#define NP 500000
#define NG4 (NN * 32)   // gather work items (float4 granularity)

// ---- scratch (device globals) ----
__device__ __align__(16) float g_x[NN * DD];        // final node features (linkpred input)
__device__ __align__(16) float g_xnorm[NN * DD];    // fp32 aggregate input
// fp16 hi/lo split planes (GEMM A operands)
__device__ __align__(16) __half g_xs_hi[NN * DD];
__device__ __align__(16) __half g_xs_lo[NN * DD];
__device__ __align__(16) __half g_as_hi[NN * DD];
__device__ __align__(16) __half g_as_lo[NN * DD];
__device__ __align__(16) __half g_hs_hi[NN * DD];
__device__ __align__(16) __half g_hs_lo[NN * DD];
__device__ int g_deg_s[NN];
__device__ int g_deg_r[NN];
__device__ int g_rowstart[NN + 1];
__device__ int g_cursor[NN];
__device__ int g_esrc[NE];
__device__ unsigned g_ticket;
// transposed fp16 weights: Wt[n][k] = W[k][n]
__device__ __align__(16) __half g_w1t[DD * 256];
__device__ __align__(16) __half g_w2t[DD * 256];
__device__ __align__(16) __half g_wat[DD * DD];

// ---- helpers ----
__device__ __forceinline__ uint32_t smem_u32(const void* p) {
    uint32_t a;
    asm("{.reg .u64 t; cvta.to.shared.u64 t, %1; cvt.u32.u64 %0, t;}" : "=r"(a) : "l"(p));
    return a;
}
#define LDSM_X4(r, a) \
    asm volatile("ldmatrix.sync.aligned.m8n8.x4.shared.b16 {%0,%1,%2,%3}, [%4];" \
        : "=r"((r)[0]), "=r"((r)[1]), "=r"((r)[2]), "=r"((r)[3]) : "r"(a))
__device__ __forceinline__ void hmma(float* d, const uint32_t* a, const uint32_t* b) {
    asm volatile(
        "mma.sync.aligned.m16n8k16.row.col.f32.f16.f16.f32 "
        "{%0,%1,%2,%3}, {%4,%5,%6,%7}, {%8,%9}, {%0,%1,%2,%3};"
        : "+f"(d[0]), "+f"(d[1]), "+f"(d[2]), "+f"(d[3])
        : "r"(a[0]), "r"(a[1]), "r"(a[2]), "r"(a[3]), "r"(b[0]), "r"(b[1]));
}
// fp16 hi/lo split via packed cvt.rn.f16x2.f32 — bit-identical to scalar __float2half_rn
__device__ __forceinline__ uint32_t pack_h2(float a, float b, uint32_t& lo_out) {
    __half2 h = __floats2half2_rn(a, b);
    float2 hf = __half22float2(h);
    __half2 l = __floats2half2_rn(a - hf.x, b - hf.y);
    lo_out = *reinterpret_cast<uint32_t*>(&l);
    return *reinterpret_cast<uint32_t*>(&h);
}
#define CP_ASYNC16(dst, src) \
    asm volatile("cp.async.cg.shared.global [%0], [%1], 16;" :: "r"(dst), "l"(src))
#define CP_COMMIT() asm volatile("cp.async.commit_group;" ::: "memory")
#define CP_WAIT_1() asm volatile("cp.async.wait_group 1;" ::: "memory")
#define CP_WAIT_0() asm volatile("cp.async.wait_group 0;" ::: "memory")
#define CP_WAIT_ALL() asm volatile("cp.async.wait_all;" ::: "memory")

#define RS 80                 // smem row stride in bytes (conflict-free for ldmatrix)
#define BUF (128 * RS)        // 10240 B per matrix buffer
#define STG3 (3 * BUF)        // Ah+Al+B per stage
#define DSMEM_LG (3 * STG3)   // layer gemm: 3-stage ring = 90KB
#define DSMEM_LP (8 * BUF)    // linkpred: 4x B-chunks + 2x (Ah,Al) stages = 80KB

// ---------------------------------------------------------------------------
// 1) prep: transpose+convert weights to fp16, init degree arrays, reset ticket
__global__ void k_prep_all(const float* __restrict__ W1, const float* __restrict__ W2,
                           const float* __restrict__ Wa) {
    int i = blockIdx.x * blockDim.x + threadIdx.x;
    if (i < DD * 256) {
        int n = i >> 8, k = i & 255;
        g_w1t[i] = __float2half_rn(W1[k * DD + n]);
        g_w2t[i] = __float2half_rn(W2[k * DD + n]);
    }
    if (i < DD * DD) {
        int n = i >> 7, k = i & 127;
        g_wat[i] = __float2half_rn(Wa[k * DD + n]);
    }
    if (i < NN) { g_deg_s[i] = 1; g_deg_r[i] = 1; }
    if (i == 0) g_ticket = 0;
}

// 2) count degrees; last block performs the exclusive scan (ticket pattern)
__global__ void k_count_scan(const int* __restrict__ senders, const int* __restrict__ receivers) {
    int stride = gridDim.x * blockDim.x;
    for (int e = blockIdx.x * blockDim.x + threadIdx.x; e < NE; e += stride) {
        atomicAdd(&g_deg_s[senders[e]], 1);
        atomicAdd(&g_deg_r[receivers[e]], 1);
    }
    __threadfence();
    __shared__ unsigned s_last;
    __syncthreads();
    if (threadIdx.x == 0) s_last = atomicAdd(&g_ticket, 1);
    __syncthreads();
    if (s_last != gridDim.x - 1) return;

    __shared__ int ss[256];
    int t = threadIdx.x;
    const int chunk = (NN + 255) / 256;
    int beg = t * chunk;
    int end = beg + chunk; if (end > NN) end = NN;
    int s = 0;
    for (int i = beg; i < end; i++) s += __ldcg(&g_deg_r[i]) - 1;
    ss[t] = s;
    __syncthreads();
    for (int off = 1; off < 256; off <<= 1) {
        int v = (t >= off) ? ss[t - off] : 0;
        __syncthreads();
        ss[t] += v;
        __syncthreads();
    }
    int run = (t == 0) ? 0 : ss[t - 1];
    for (int i = beg; i < end; i++) {
        g_rowstart[i] = run;
        g_cursor[i] = run;
        run += __ldcg(&g_deg_r[i]) - 1;
    }
    if (t == 255) g_rowstart[NN] = ss[255];
}

// 3) fused: CSR scatter + gather (emb -> x split planes + xnorm fp32)
//    g_x is NOT written here (dead store — gemm2 fully overwrites it before
//    linkpred reads it; validated in R16 with identical rel_err).
__global__ void k_scatter_gather(const int* __restrict__ senders,
                                 const int* __restrict__ receivers,
                                 const int* __restrict__ node_ids,
                                 const float* __restrict__ emb) {
    int i = blockIdx.x * blockDim.x + threadIdx.x;
    if (i < NG4) {
        int node = i >> 5;
        int q = i & 31;
        int src = node_ids[node];
        float4 v = ((const float4*)emb)[src * 32 + q];
        uint32_t l0, l1;
        uint2 H;
        H.x = pack_h2(v.x, v.y, l0);
        H.y = pack_h2(v.z, v.w, l1);
        ((uint2*)g_xs_hi)[i] = H;
        ((uint2*)g_xs_lo)[i] = make_uint2(l0, l1);
        float sc = rsqrtf((float)g_deg_s[node]);
        v.x *= sc; v.y *= sc; v.z *= sc; v.w *= sc;
        ((float4*)g_xnorm)[i] = v;
    } else {
        int e = i - NG4;
        if (e < NE) {
            int r = receivers[e];
            int pos = atomicAdd(&g_cursor[r], 1);
            g_esrc[pos] = senders[e];
        }
    }
}

__device__ __forceinline__ float4 f4add(float4 a, float4 b) {
    return make_float4(a.x + b.x, a.y + b.y, a.z + b.z, a.w + b.w);
}

// 4) aggregate: warp per node; writes agg as fp16 hi/lo planes
__global__ void k_aggregate() {
    int gw = (blockIdx.x * blockDim.x + threadIdx.x) >> 5;
    if (gw >= NN) return;
    int lane = threadIdx.x & 31;
    const float4* __restrict__ xn = (const float4*)g_xnorm;
    float4 acc = xn[gw * 32 + lane];
    int s = g_rowstart[gw], e = g_rowstart[gw + 1];
    int j = s;
    for (; j + 8 <= e; j += 8) {
        int s0 = g_esrc[j], s1 = g_esrc[j + 1], s2 = g_esrc[j + 2], s3 = g_esrc[j + 3];
        int s4 = g_esrc[j + 4], s5 = g_esrc[j + 5], s6 = g_esrc[j + 6], s7 = g_esrc[j + 7];
        float4 a0 = xn[s0 * 32 + lane];
        float4 a1 = xn[s1 * 32 + lane];
        float4 a2 = xn[s2 * 32 + lane];
        float4 a3 = xn[s3 * 32 + lane];
        float4 a4 = xn[s4 * 32 + lane];
        float4 a5 = xn[s5 * 32 + lane];
        float4 a6 = xn[s6 * 32 + lane];
        float4 a7 = xn[s7 * 32 + lane];
        acc = f4add(acc, f4add(f4add(f4add(a0, a1), f4add(a2, a3)),
                               f4add(f4add(a4, a5), f4add(a6, a7))));
    }
    for (; j < e; j++) acc = f4add(acc, xn[g_esrc[j] * 32 + lane]);
    float cnt = (float)(e - s + 1);
    float sc = rsqrtf(cnt) / cnt;
    acc.x *= sc; acc.y *= sc; acc.z *= sc; acc.w *= sc;
    uint32_t l0, l1;
    uint2 H;
    H.x = pack_h2(acc.x, acc.y, l0);
    H.y = pack_h2(acc.z, acc.w, l1);
    ((uint2*)g_as_hi)[gw * 32 + lane] = H;
    ((uint2*)g_as_lo)[gw * 32 + lane] = make_uint2(l0, l1);
}

// MMA compute for one staged chunk (fp16, 2-term split on A)
__device__ __forceinline__ void chunk_compute(
    float (*acc)[8][4], uint32_t aHi, uint32_t aLo, uint32_t aB,
    int wm, int wn, int lane)
{
    int a_row = lane & 15, a_k = (lane >> 4) * 16;
    int b_addr_row = (lane & 7) + 8 * ((lane >> 4) & 1);
    int b_k = ((lane >> 3) & 1) * 16;
#pragma unroll
    for (int ks = 0; ks < 2; ks++) {
        uint32_t ah[2][4], al[2][4], b[8][2];
#pragma unroll
        for (int mt = 0; mt < 2; mt++) {
            uint32_t ao = (uint32_t)((wm * 32 + mt * 16 + a_row) * RS + ks * 32 + a_k);
            LDSM_X4(ah[mt], aHi + ao);
            LDSM_X4(al[mt], aLo + ao);
        }
#pragma unroll
        for (int np = 0; np < 4; np++) {
            uint32_t bo = (uint32_t)((wn * 64 + np * 16 + b_addr_row) * RS + ks * 32 + b_k);
            uint32_t r4[4];
            LDSM_X4(r4, aB + bo);
            b[2 * np][0] = r4[0]; b[2 * np][1] = r4[1];
            b[2 * np + 1][0] = r4[2]; b[2 * np + 1][1] = r4[3];
        }
#pragma unroll
        for (int mt = 0; mt < 2; mt++)
#pragma unroll
            for (int nt = 0; nt < 8; nt++) {
                hmma(acc[mt][nt], ah[mt], b[nt]);
                hmma(acc[mt][nt], al[mt], b[nt]);
            }
    }
}

// ---- HMMA layer GEMM: cp.async 3-stage ring, ONE barrier per chunk, K=256 ----
template <bool RELU, bool WRITE_XN, bool SPLIT_OUT>
__global__ void __launch_bounds__(256, 2) k_mgemm_layer(
    const __half* __restrict__ Xhi, const __half* __restrict__ Xlo,
    const __half* __restrict__ Ahi, const __half* __restrict__ Alo,
    const __half* __restrict__ Bw, const float* __restrict__ bias,
    __half* __restrict__ Chi, __half* __restrict__ Clo, float* __restrict__ Cf,
    float* __restrict__ XN, const int* __restrict__ deg, int M)
{
    extern __shared__ __align__(16) uint8_t dsm[];
    int tid = threadIdx.x;
    int lane = tid & 31, wid = tid >> 5;
    int wm = wid & 3, wn = wid >> 2;
    int blk = blockIdx.x * 128;

    float acc[2][8][4];
#pragma unroll
    for (int mt = 0; mt < 2; mt++)
#pragma unroll
        for (int nt = 0; nt < 8; nt++)
#pragma unroll
            for (int i = 0; i < 4; i++) acc[mt][nt][i] = 0.f;

    int srow = tid >> 1, half = tid & 1;
    int grow_s = blk + srow;
    int crow_s = grow_s < M ? grow_s : M - 1;
    int off = srow * RS + half * 32;

    uint32_t sbase = smem_u32(dsm);
    const char* xh = (const char*)(Xhi + crow_s * DD) + half * 32;
    const char* xl = (const char*)(Xlo + crow_s * DD) + half * 32;
    const char* gh = (const char*)(Ahi + crow_s * DD) + half * 32;
    const char* gl = (const char*)(Alo + crow_s * DD) + half * 32;
    const char* bw = (const char*)(Bw + srow * 256) + half * 32;

    auto issue = [&](int c) {
        uint32_t st = sbase + (c % 3) * STG3 + off;
        int kb2 = (c & 3) * 64;
        const char* sh = (c < 4) ? xh : gh;
        const char* sl = (c < 4) ? xl : gl;
        CP_ASYNC16(st, sh + kb2);
        CP_ASYNC16(st + 16, sh + kb2 + 16);
        CP_ASYNC16(st + BUF, sl + kb2);
        CP_ASYNC16(st + BUF + 16, sl + kb2 + 16);
        CP_ASYNC16(st + 2 * BUF, bw + c * 64);
        CP_ASYNC16(st + 2 * BUF + 16, bw + c * 64 + 16);
        CP_COMMIT();
    };

    issue(0);
    issue(1);
#pragma unroll
    for (int c = 0; c < 8; c++) {
        if (c < 7) CP_WAIT_1(); else CP_WAIT_0();   // group c landed
        __syncthreads();                             // visibility + slot recycle
        if (c + 2 <= 7) issue(c + 2);                // slot (c+2)%3 last read in compute(c-1)
        uint32_t st = sbase + (c % 3) * STG3;
        chunk_compute(acc, st, st + BUF, st + 2 * BUF, wm, wn, lane);
    }

    // epilogue
#pragma unroll
    for (int mt = 0; mt < 2; mt++) {
        int r0 = blk + wm * 32 + mt * 16 + (lane >> 2);
        int r1 = r0 + 8;
        float s0 = 1.f, s1 = 1.f;
        if (WRITE_XN) {
            s0 = rsqrtf((float)deg[r0 < M ? r0 : M - 1]);
            s1 = rsqrtf((float)deg[r1 < M ? r1 : M - 1]);
        }
#pragma unroll
        for (int nt = 0; nt < 8; nt++) {
            int cc = wn * 64 + nt * 8 + (lane & 3) * 2;
            float2 bv = *(const float2*)(bias + cc);
            float v0 = acc[mt][nt][0] + bv.x;
            float v1 = acc[mt][nt][1] + bv.y;
            float v2 = acc[mt][nt][2] + bv.x;
            float v3 = acc[mt][nt][3] + bv.y;
            if (RELU) {
                v0 = fmaxf(v0, 0.f); v1 = fmaxf(v1, 0.f);
                v2 = fmaxf(v2, 0.f); v3 = fmaxf(v3, 0.f);
            }
            if (r0 < M) {
                if (SPLIT_OUT) {
                    uint32_t lo;
                    uint32_t hi = pack_h2(v0, v1, lo);
                    *(uint32_t*)((char*)Chi + r0 * 256 + cc * 2) = hi;
                    *(uint32_t*)((char*)Clo + r0 * 256 + cc * 2) = lo;
                } else {
                    *(float2*)(Cf + r0 * DD + cc) = make_float2(v0, v1);
                }
                if (WRITE_XN) *(float2*)(XN + r0 * DD + cc) = make_float2(v0 * s0, v1 * s0);
            }
            if (r1 < M) {
                if (SPLIT_OUT) {
                    uint32_t lo;
                    uint32_t hi = pack_h2(v2, v3, lo);
                    *(uint32_t*)((char*)Chi + r1 * 256 + cc * 2) = hi;
                    *(uint32_t*)((char*)Clo + r1 * 256 + cc * 2) = lo;
                } else {
                    *(float2*)(Cf + r1 * DD + cc) = make_float2(v2, v3);
                }
                if (WRITE_XN) *(float2*)(XN + r1 * DD + cc) = make_float2(v2 * s1, v3 * s1);
            }
        }
    }
}

// ---- HMMA link predictor, K=128: B fully smem-resident, 2 chunks per barrier ----
__global__ void __launch_bounds__(256, 2) k_mlinkpred(
    const float* __restrict__ H, const int* __restrict__ pairs,
    const __half* __restrict__ Bw,
    const float* __restrict__ ba, const float* __restrict__ Wb,
    const float* __restrict__ bb, float* __restrict__ out)
{
    extern __shared__ __align__(16) uint8_t dsm[];
    __shared__ float sacc[128];
    int tid = threadIdx.x;
    int lane = tid & 31, wid = tid >> 5;
    int wm = wid & 3, wn = wid >> 2;
    int blk = blockIdx.x * 128;

    if (tid < 128) sacc[tid] = 0.f;

    float acc[2][8][4];
#pragma unroll
    for (int mt = 0; mt < 2; mt++)
#pragma unroll
        for (int nt = 0; nt < 8; nt++)
#pragma unroll
            for (int i = 0; i < 4; i++) acc[mt][nt][i] = 0.f;

    int srow = tid >> 1, half = tid & 1;
    int grow_s = blk + srow;
    int crow_s = grow_s < NP ? grow_s : NP - 1;
    int ia = pairs[2 * crow_s];
    int ib = pairs[2 * crow_s + 1];
    int off = srow * RS + half * 32;

    // smem map: B chunks 0-3 at c*BUF; A stages at 4*BUF.. (Ah0,Al0,Ah1,Al1)
    uint32_t aB0 = smem_u32(dsm);
    uint32_t aAh0 = aB0 + 4 * BUF, aAl0 = aB0 + 5 * BUF;
    uint32_t aAh1 = aB0 + 6 * BUF, aAl1 = aB0 + 7 * BUF;

    // prefetch ALL of Wa (4 chunk-buffers) via cp.async — leaves the chunk loop
    {
        const char* bw = (const char*)Bw + srow * 256 + half * 32;
#pragma unroll
        for (int c = 0; c < 4; c++) {
            CP_ASYNC16(aB0 + c * BUF + off, bw + c * 64);
            CP_ASYNC16(aB0 + c * BUF + off + 16, bw + c * 64 + 16);
        }
    }

    // stage A (products -> fp16 hi/lo) for one chunk
    auto stageA = [&](int c, uint8_t* sAh, uint8_t* sAl) {
        int kb = c * 32;
        const float4* pa = (const float4*)(H + ia * DD + kb) + half * 4;
        const float4* pb = (const float4*)(H + ib * DD + kb) + half * 4;
        float4 pv[4];
#pragma unroll
        for (int i = 0; i < 4; i++) {
            float4 x = pa[i], y = pb[i];
            pv[i] = make_float4(x.x * y.x, x.y * y.y, x.z * y.z, x.w * y.w);
        }
        uint4 H0, L0, H1, L1;
        H0.x = pack_h2(pv[0].x, pv[0].y, L0.x);
        H0.y = pack_h2(pv[0].z, pv[0].w, L0.y);
        H0.z = pack_h2(pv[1].x, pv[1].y, L0.z);
        H0.w = pack_h2(pv[1].z, pv[1].w, L0.w);
        H1.x = pack_h2(pv[2].x, pv[2].y, L1.x);
        H1.y = pack_h2(pv[2].z, pv[2].w, L1.y);
        H1.z = pack_h2(pv[3].x, pv[3].y, L1.z);
        H1.w = pack_h2(pv[3].z, pv[3].w, L1.w);
        *(uint4*)(sAh + off) = H0;
        *(uint4*)(sAh + off + 16) = H1;
        *(uint4*)(sAl + off) = L0;
        *(uint4*)(sAl + off + 16) = L1;
    };

#pragma unroll
    for (int i = 0; i < 2; i++) {
        stageA(2 * i, dsm + 4 * BUF, dsm + 5 * BUF);
        stageA(2 * i + 1, dsm + 6 * BUF, dsm + 7 * BUF);
        if (i == 0) CP_WAIT_ALL();          // B resident before first compute
        __syncthreads();
        chunk_compute(acc, aAh0, aAl0, aB0 + (2 * i) * BUF, wm, wn, lane);
        chunk_compute(acc, aAh1, aAl1, aB0 + (2 * i + 1) * BUF, wm, wn, lane);
        __syncthreads();
    }

    // epilogue: per-row sum of relu(acc + ba[c]) * Wb[c]
#pragma unroll
    for (int mt = 0; mt < 2; mt++) {
        int lr0 = wm * 32 + mt * 16 + (lane >> 2);
        float p0 = 0.f, p1 = 0.f;
#pragma unroll
        for (int nt = 0; nt < 8; nt++) {
            int cc = wn * 64 + nt * 8 + (lane & 3) * 2;
            float2 bav = *(const float2*)(ba + cc);
            float2 wbv = *(const float2*)(Wb + cc);
            p0 += fmaxf(acc[mt][nt][0] + bav.x, 0.f) * wbv.x
                + fmaxf(acc[mt][nt][1] + bav.y, 0.f) * wbv.y;
            p1 += fmaxf(acc[mt][nt][2] + bav.x, 0.f) * wbv.x
                + fmaxf(acc[mt][nt][3] + bav.y, 0.f) * wbv.y;
        }
        p0 += __shfl_xor_sync(0xffffffffu, p0, 1);
        p0 += __shfl_xor_sync(0xffffffffu, p0, 2);
        p1 += __shfl_xor_sync(0xffffffffu, p1, 1);
        p1 += __shfl_xor_sync(0xffffffffu, p1, 2);
        if ((lane & 3) == 0) {
            atomicAdd(&sacc[lr0], p0);
            atomicAdd(&sacc[lr0 + 8], p1);
        }
    }
    __syncthreads();
    if (tid < 128) {
        int row = blk + tid;
        if (row < NP) out[row] = sacc[tid] + bb[0];
    }
}

// ---------------------------------------------------------------------------
extern "C" void kernel_launch(void* const* d_in, const int* in_sizes, int n_in,
                              void* d_out, int out_size) {
    const int*   node_ids  = (const int*)d_in[0];
    const int*   senders   = (const int*)d_in[1];
    const int*   receivers = (const int*)d_in[2];
    const int*   pairs     = (const int*)d_in[3];
    const float* emb       = (const float*)d_in[4];
    const float* W1        = (const float*)d_in[5];
    const float* b1        = (const float*)d_in[6];
    const float* W2        = (const float*)d_in[7];
    const float* b2        = (const float*)d_in[8];
    const float* Wa        = (const float*)d_in[9];
    const float* ba        = (const float*)d_in[10];
    const float* Wb        = (const float*)d_in[11];
    const float* bb        = (const float*)d_in[12];
    float* out = (float*)d_out;

    float *x, *xn;
    int* degs;
    __half *w1t, *w2t, *wat, *xsh, *xsl, *ash, *asl, *hsh, *hsl;
    cudaGetSymbolAddress((void**)&x,  g_x);
    cudaGetSymbolAddress((void**)&xn, g_xnorm);
    cudaGetSymbolAddress((void**)&degs, g_deg_s);
    cudaGetSymbolAddress((void**)&w1t, g_w1t);
    cudaGetSymbolAddress((void**)&w2t, g_w2t);
    cudaGetSymbolAddress((void**)&wat, g_wat);
    cudaGetSymbolAddress((void**)&xsh, g_xs_hi);
    cudaGetSymbolAddress((void**)&xsl, g_xs_lo);
    cudaGetSymbolAddress((void**)&ash, g_as_hi);
    cudaGetSymbolAddress((void**)&asl, g_as_lo);
    cudaGetSymbolAddress((void**)&hsh, g_hs_hi);
    cudaGetSymbolAddress((void**)&hsl, g_hs_lo);

    cudaFuncSetAttribute(k_mgemm_layer<true, true, true>,
                         cudaFuncAttributeMaxDynamicSharedMemorySize, DSMEM_LG);
    cudaFuncSetAttribute(k_mgemm_layer<false, false, false>,
                         cudaFuncAttributeMaxDynamicSharedMemorySize, DSMEM_LG);
    cudaFuncSetAttribute(k_mlinkpred,
                         cudaFuncAttributeMaxDynamicSharedMemorySize, DSMEM_LP);

    const int vb = (NG4 + 255) / 256;   // 12500

    k_prep_all<<<(NN + 255) / 256, 256>>>(W1, W2, Wa);
    k_count_scan<<<2048, 256>>>(senders, receivers);
    k_scatter_gather<<<(NG4 + NE + 255) / 256, 256>>>(senders, receivers, node_ids, emb);
    k_aggregate<<<vb, 256>>>();

    // layer 1: [x|agg] -> h split planes (relu) + xnorm fp32 for layer-2 aggregate
    k_mgemm_layer<true, true, true><<<(NN + 127) / 128, 256, DSMEM_LG>>>(
        xsh, xsl, ash, asl, w1t, b1, hsh, hsl, nullptr, xn, degs, NN);

    // layer 2: [h|agg] -> x fp32 (no relu)
    k_aggregate<<<vb, 256>>>();
    k_mgemm_layer<false, false, false><<<(NN + 127) / 128, 256, DSMEM_LG>>>(
        hsh, hsl, ash, asl, w2t, b2, nullptr, nullptr, x, nullptr, degs, NN);

    // link predictor
    k_mlinkpred<<<(NP + 127) / 128, 256, DSMEM_LP>>>(
        x, pairs, wat, ba, Wb, bb, out);
}